// round 1
// baseline (speedup 1.0000x reference)
#include <cuda_runtime.h>
#include <math.h>

// ---------------------------------------------------------------------------
// LinOSS layer: B=16, N=4096, q=256
//   Bu = u @ W_B^T + b_B                        (GEMM1)
//   y  = IM scan of 2x2 diagonal-block recurrence over N   (chunked scan)
//   h  = y @ W_C^T + u @ W_D^T + b_C + b_D      (GEMM2, fused epilogue)
//   g  = gelu_exact(h); out = g*sigmoid(g) + u
// Outputs: [out (B,N,q) | y (B,N,q)] concatenated in d_out.
// ---------------------------------------------------------------------------

namespace {
constexpr int kB = 16;
constexpr int kN = 4096;
constexpr int kQ = 256;
constexpr int kM = kB * kN;                 // 65536 rows
constexpr float kDT = 1.0f / 4096.0f;
constexpr int kNChunk = 32;
constexpr int kCLen = kN / kNChunk;         // 128 (power of two)
}  // namespace

// Device scratch (static allocation; no cudaMalloc allowed)
__device__ float  g_Bu[(size_t)kM * kQ];              // 64 MB
__device__ float2 g_end[kB * kNChunk * kQ];           // chunk end states
__device__ float2 g_init[kB * kNChunk * kQ];          // chunk init states

// ---------------------------------------------------------------------------
// GEMM1: g_Bu = U @ W^T + bias   (M=65536, N=256, K=256, NT layout)
// 128x128 tile, BK=8, 256 threads, 8x8 per-thread micro-tile.
// ---------------------------------------------------------------------------
__global__ __launch_bounds__(256) void k_gemm_bu(
    const float* __restrict__ U, const float* __restrict__ W,
    const float* __restrict__ bias)
{
    constexpr int BM = 128, BN = 128, BK = 8;
    __shared__ float As[BK][BM];
    __shared__ float Bs[BK][BN];

    const int tid = threadIdx.x;
    const int bm = blockIdx.y, bn = blockIdx.x;
    const int tx = tid & 15, ty = tid >> 4;
    const int lr = tid >> 1;           // 0..127 load row
    const int lc = (tid & 1) << 2;     // 0 or 4 (float4 within 8-wide k slab)

    const float* aPtr = U + ((size_t)(bm * BM + lr)) * kQ + lc;
    const float* bPtr = W + ((size_t)(bn * BN + lr)) * kQ + lc;

    float acc[8][8];
#pragma unroll
    for (int i = 0; i < 8; i++)
#pragma unroll
        for (int j = 0; j < 8; j++) acc[i][j] = 0.0f;

    for (int k0 = 0; k0 < kQ; k0 += BK) {
        float4 av = *reinterpret_cast<const float4*>(aPtr + k0);
        float4 bv = *reinterpret_cast<const float4*>(bPtr + k0);
        As[lc + 0][lr] = av.x; As[lc + 1][lr] = av.y;
        As[lc + 2][lr] = av.z; As[lc + 3][lr] = av.w;
        Bs[lc + 0][lr] = bv.x; Bs[lc + 1][lr] = bv.y;
        Bs[lc + 2][lr] = bv.z; Bs[lc + 3][lr] = bv.w;
        __syncthreads();
#pragma unroll
        for (int k = 0; k < BK; k++) {
            float af[8], bf[8];
#pragma unroll
            for (int i = 0; i < 8; i++) af[i] = As[k][ty * 8 + i];
#pragma unroll
            for (int j = 0; j < 8; j++) bf[j] = Bs[k][tx * 8 + j];
#pragma unroll
            for (int i = 0; i < 8; i++)
#pragma unroll
                for (int j = 0; j < 8; j++)
                    acc[i][j] = fmaf(af[i], bf[j], acc[i][j]);
        }
        __syncthreads();
    }

    float bv[8];
#pragma unroll
    for (int j = 0; j < 8; j++) bv[j] = bias[bn * BN + tx * 8 + j];

#pragma unroll
    for (int i = 0; i < 8; i++) {
        size_t row = (size_t)bm * BM + ty * 8 + i;
        float* dst = &g_Bu[row * kQ + bn * BN + tx * 8];
        float4 v0, v1;
        v0.x = acc[i][0] + bv[0]; v0.y = acc[i][1] + bv[1];
        v0.z = acc[i][2] + bv[2]; v0.w = acc[i][3] + bv[3];
        v1.x = acc[i][4] + bv[4]; v1.y = acc[i][5] + bv[5];
        v1.z = acc[i][6] + bv[6]; v1.w = acc[i][7] + bv[7];
        *reinterpret_cast<float4*>(dst) = v0;
        *reinterpret_cast<float4*>(dst + 4) = v1;
    }
}

// ---------------------------------------------------------------------------
// Scan pass A: per-chunk end states from zero init.
// idx -> (b, chunk, qi); coalesced over qi; reads g_Bu stride kQ.
// Step: x' = s*x - dt*s*a*z + fx ; z' = dt*s*x + s*z + fz
//   fx = dt*s*Bu, fz = dt*fx
// ---------------------------------------------------------------------------
__global__ __launch_bounds__(256) void k_scan_ends(const float* __restrict__ A)
{
    int idx = blockIdx.x * blockDim.x + threadIdx.x;   // < kB*kNChunk*kQ
    int qi = idx & (kQ - 1);
    int c  = (idx >> 8) & (kNChunk - 1);
    int b  = idx >> 13;

    float av  = A[qi];
    float s   = 1.0f / (1.0f + kDT * kDT * av);
    float dts = kDT * s;
    float dsa = dts * av;

    const float* p = g_Bu + ((size_t)(b * kN + c * kCLen)) * kQ + qi;
    float x = 0.0f, z = 0.0f;
#pragma unroll 4
    for (int n = 0; n < kCLen; n++) {
        float bu = p[(size_t)n * kQ];
        float fx = dts * bu;
        float xn = fmaf(s, x, fmaf(-dsa, z, fx));
        float zn = fmaf(dts, x, fmaf(s, z, kDT * fx));
        x = xn; z = zn;
    }
    g_end[idx] = make_float2(x, z);
}

// ---------------------------------------------------------------------------
// Scan pass B: sequential chunk-prefix combine per (b, qi).
// P = M^kCLen via repeated squaring (kCLen = 128 = 2^7).
// ---------------------------------------------------------------------------
__global__ __launch_bounds__(256) void k_scan_combine(const float* __restrict__ A)
{
    int idx = blockIdx.x * blockDim.x + threadIdx.x;  // < kB*kQ
    int qi = idx & (kQ - 1);
    int b  = idx >> 8;

    float av  = A[qi];
    float s   = 1.0f / (1.0f + kDT * kDT * av);
    float dts = kDT * s;
    float dsa = dts * av;

    float p00 = s, p01 = -dsa, p10 = dts, p11 = s;
#pragma unroll
    for (int i = 0; i < 7; i++) {          // M^(2^7)
        float t   = p00 + p11;
        float bc  = p01 * p10;
        float n00 = fmaf(p00, p00, bc);
        float n01 = p01 * t;
        float n10 = p10 * t;
        float n11 = fmaf(p11, p11, bc);
        p00 = n00; p01 = n01; p10 = n10; p11 = n11;
    }

    float x = 0.0f, z = 0.0f;
    for (int c = 0; c < kNChunk; c++) {
        int gi = (b * kNChunk + c) * kQ + qi;
        g_init[gi] = make_float2(x, z);
        float2 e = g_end[gi];
        float xn = fmaf(p00, x, fmaf(p01, z, e.x));
        float zn = fmaf(p10, x, fmaf(p11, z, e.y));
        x = xn; z = zn;
    }
}

// ---------------------------------------------------------------------------
// Scan pass C: re-scan each chunk from corrected init, emit y (= z each step).
// ---------------------------------------------------------------------------
__global__ __launch_bounds__(256) void k_scan_emit(
    const float* __restrict__ A, float* __restrict__ Yout)
{
    int idx = blockIdx.x * blockDim.x + threadIdx.x;
    int qi = idx & (kQ - 1);
    int c  = (idx >> 8) & (kNChunk - 1);
    int b  = idx >> 13;

    float av  = A[qi];
    float s   = 1.0f / (1.0f + kDT * kDT * av);
    float dts = kDT * s;
    float dsa = dts * av;

    size_t off = ((size_t)(b * kN + c * kCLen)) * kQ + qi;
    const float* p = g_Bu + off;
    float* yp = Yout + off;

    float2 st = g_init[idx];
    float x = st.x, z = st.y;
#pragma unroll 4
    for (int n = 0; n < kCLen; n++) {
        float bu = p[(size_t)n * kQ];
        float fx = dts * bu;
        float xn = fmaf(s, x, fmaf(-dsa, z, fx));
        float zn = fmaf(dts, x, fmaf(s, z, kDT * fx));
        x = xn; z = zn;
        yp[(size_t)n * kQ] = z;
    }
}

// ---------------------------------------------------------------------------
// GEMM2 (fused output): h = Y@W_C^T + U@W_D^T + b_C + b_D
//   g = 0.5*h*(1+erf(h/sqrt(2))); out = g*sigmoid(g) + u
// Two-phase K loop (K = 256 + 256) over the same 128x128 tile machinery.
// ---------------------------------------------------------------------------
__global__ __launch_bounds__(256) void k_gemm_out(
    const float* __restrict__ Y, const float* __restrict__ U,
    const float* __restrict__ WC, const float* __restrict__ WD,
    const float* __restrict__ bC, const float* __restrict__ bD,
    float* __restrict__ Out)
{
    constexpr int BM = 128, BN = 128, BK = 8;
    __shared__ float As[BK][BM];
    __shared__ float Bs[BK][BN];

    const int tid = threadIdx.x;
    const int bm = blockIdx.y, bn = blockIdx.x;
    const int tx = tid & 15, ty = tid >> 4;
    const int lr = tid >> 1;
    const int lc = (tid & 1) << 2;

    float acc[8][8];
#pragma unroll
    for (int i = 0; i < 8; i++)
#pragma unroll
        for (int j = 0; j < 8; j++) acc[i][j] = 0.0f;

#pragma unroll
    for (int phase = 0; phase < 2; phase++) {
        const float* Ap = phase ? U : Y;
        const float* Wp = phase ? WD : WC;
        const float* aPtr = Ap + ((size_t)(bm * BM + lr)) * kQ + lc;
        const float* bPtr = Wp + ((size_t)(bn * BN + lr)) * kQ + lc;
        for (int k0 = 0; k0 < kQ; k0 += BK) {
            float4 av = *reinterpret_cast<const float4*>(aPtr + k0);
            float4 bv = *reinterpret_cast<const float4*>(bPtr + k0);
            As[lc + 0][lr] = av.x; As[lc + 1][lr] = av.y;
            As[lc + 2][lr] = av.z; As[lc + 3][lr] = av.w;
            Bs[lc + 0][lr] = bv.x; Bs[lc + 1][lr] = bv.y;
            Bs[lc + 2][lr] = bv.z; Bs[lc + 3][lr] = bv.w;
            __syncthreads();
#pragma unroll
            for (int k = 0; k < BK; k++) {
                float af[8], bf[8];
#pragma unroll
                for (int i = 0; i < 8; i++) af[i] = As[k][ty * 8 + i];
#pragma unroll
                for (int j = 0; j < 8; j++) bf[j] = Bs[k][tx * 8 + j];
#pragma unroll
                for (int i = 0; i < 8; i++)
#pragma unroll
                    for (int j = 0; j < 8; j++)
                        acc[i][j] = fmaf(af[i], bf[j], acc[i][j]);
            }
            __syncthreads();
        }
    }

    const int col0 = bn * BN + tx * 8;
    float bias[8];
#pragma unroll
    for (int j = 0; j < 8; j++) bias[j] = bC[col0 + j] + bD[col0 + j];

#pragma unroll
    for (int i = 0; i < 8; i++) {
        size_t row = (size_t)bm * BM + ty * 8 + i;
        const float* up = &U[row * kQ + col0];
        float4 u0 = *reinterpret_cast<const float4*>(up);
        float4 u1 = *reinterpret_cast<const float4*>(up + 4);
        float uv[8] = {u0.x, u0.y, u0.z, u0.w, u1.x, u1.y, u1.z, u1.w};
        float ov[8];
#pragma unroll
        for (int j = 0; j < 8; j++) {
            float h = acc[i][j] + bias[j];
            float g = 0.5f * h * (1.0f + erff(h * 0.70710678118654752f));
            float sg = 1.0f / (1.0f + expf(-g));
            ov[j] = fmaf(g, sg, uv[j]);
        }
        float* dst = &Out[row * kQ + col0];
        float4 v0, v1;
        v0.x = ov[0]; v0.y = ov[1]; v0.z = ov[2]; v0.w = ov[3];
        v1.x = ov[4]; v1.y = ov[5]; v1.z = ov[6]; v1.w = ov[7];
        *reinterpret_cast<float4*>(dst) = v0;
        *reinterpret_cast<float4*>(dst + 4) = v1;
    }
}

// ---------------------------------------------------------------------------
// Launch
// ---------------------------------------------------------------------------
extern "C" void kernel_launch(void* const* d_in, const int* in_sizes, int n_in,
                              void* d_out, int out_size)
{
    const float* u  = (const float*)d_in[0];
    const float* a  = (const float*)d_in[1];
    const float* WB = (const float*)d_in[2];
    const float* bB = (const float*)d_in[3];
    const float* WC = (const float*)d_in[4];
    const float* bC = (const float*)d_in[5];
    const float* WD = (const float*)d_in[6];
    const float* bD = (const float*)d_in[7];

    float* out  = (float*)d_out;
    float* yout = out + (size_t)out_size / 2;   // second half: y

    dim3 gemmGrid(kQ / 128, kM / 128);          // (2, 512)
    k_gemm_bu<<<gemmGrid, 256>>>(u, WB, bB);

    int scanThreads = kB * kNChunk * kQ;        // 131072
    k_scan_ends<<<scanThreads / 256, 256>>>(a);
    k_scan_combine<<<(kB * kQ) / 256, 256>>>(a);
    k_scan_emit<<<scanThreads / 256, 256>>>(a, yout);

    k_gemm_out<<<gemmGrid, 256>>>(yout, u, WC, WD, bC, bD, out);
}

// round 3
// speedup vs baseline: 1.8810x; 1.8810x over previous
#include <cuda_runtime.h>
#include <cuda_bf16.h>
#include <math.h>
#include <stdint.h>

// ---------------------------------------------------------------------------
// LinOSS layer: B=16, N=4096, q=256 on sm_103 (HMMA mma.sync bf16 3-pass)
//   Bu = u @ W_B^T + b_B                      (GEMM1, mma.sync)
//   y  = IM scan (chunked, 3-pass)            (SIMT)
//   h  = y@W_C^T + u@W_D^T + b_C + b_D        (GEMM2, fused epilogue)
//   g  = gelu_exact(h); out = g*sigmoid(g)+u
// Output: [out | y]
// ---------------------------------------------------------------------------

namespace {
constexpr int kB = 16;
constexpr int kN = 4096;
constexpr int kQ = 256;
constexpr int kM = kB * kN;                 // 65536
constexpr float kDT = 1.0f / 4096.0f;
constexpr int kNChunk = 32;
constexpr int kCLen = kN / kNChunk;         // 128

constexpr int TM = 128, TN = 128, BK = 32;  // CTA tile, K-chunk (bf16 elems)
constexpr int SSTR = 40;                    // smem row stride in bf16 (32+8 pad)
constexpr int PL_ELEMS = TM * SSTR;         // one plane (A or B, hi or lo)
constexpr int PL_BYTES = PL_ELEMS * 2;      // 10240
constexpr int STAGE_ELEMS = 4 * PL_ELEMS;   // aHi,aLo,bHi,bLo
constexpr int STAGE_BYTES = 4 * PL_BYTES;   // 40960
constexpr int SMEM_BYTES = 2 * STAGE_BYTES; // 81920
}  // namespace

// Device scratch (static; no cudaMalloc allowed)
__device__ float  g_Bu[(size_t)kM * kQ];
__device__ float2 g_end[kB * kNChunk * kQ];
__device__ float2 g_init[kB * kNChunk * kQ];

// ---------------------------------------------------------------------------
// helpers
// ---------------------------------------------------------------------------
__device__ __forceinline__ uint32_t smem_u32(const void* p) {
    uint32_t a;
    asm("{ .reg .u64 t; cvta.to.shared.u64 t, %1; cvt.u32.u64 %0, t; }" : "=r"(a) : "l"(p));
    return a;
}
__device__ __forceinline__ uint32_t pack_hi(float a, float b, float& ra, float& rb) {
    __nv_bfloat162 h = __floats2bfloat162_rn(a, b);
    ra = a - __bfloat162float(h.x);
    rb = b - __bfloat162float(h.y);
    uint32_t u; memcpy(&u, &h, 4); return u;
}
__device__ __forceinline__ uint32_t pack2(float a, float b) {
    __nv_bfloat162 h = __floats2bfloat162_rn(a, b);
    uint32_t u; memcpy(&u, &h, 4); return u;
}
__device__ __forceinline__ void ldsm4(uint32_t (&r)[4], uint32_t addr) {
    asm volatile("ldmatrix.sync.aligned.m8n8.x4.shared.b16 {%0,%1,%2,%3}, [%4];"
                 : "=r"(r[0]), "=r"(r[1]), "=r"(r[2]), "=r"(r[3]) : "r"(addr));
}
__device__ __forceinline__ void mma16816(float* c, const uint32_t* a, const uint32_t* b) {
    asm volatile(
        "mma.sync.aligned.m16n8k16.row.col.f32.bf16.bf16.f32 "
        "{%0,%1,%2,%3}, {%4,%5,%6,%7}, {%8,%9}, {%0,%1,%2,%3};"
        : "+f"(c[0]), "+f"(c[1]), "+f"(c[2]), "+f"(c[3])
        : "r"(a[0]), "r"(a[1]), "r"(a[2]), "r"(a[3]), "r"(b[0]), "r"(b[1]));
}

// Global fp32 load of one K-chunk: A tile rows 0..127, B tile rows 0..127.
// 256 threads: thread t -> row t/2, float4 slots (t&1)*4 .. +3 of the 8-slot row.
__device__ __forceinline__ void ldg_chunk(const float* __restrict__ aSrc,
                                          const float* __restrict__ bSrc,
                                          int tid, float4 (&v)[8]) {
    const int r = tid >> 1;
    const int q = (tid & 1) * 4;
    const float4* ap = reinterpret_cast<const float4*>(aSrc + (size_t)r * kQ) + q;
    const float4* bp = reinterpret_cast<const float4*>(bSrc + (size_t)r * kQ) + q;
#pragma unroll
    for (int j = 0; j < 4; j++) { v[j] = ap[j]; v[4 + j] = bp[j]; }
}

// Split to bf16 hi/lo, store into stage planes.
__device__ __forceinline__ void sts_chunk(__nv_bfloat16* stage, int tid,
                                          const float4 (&v)[8]) {
    const int r = tid >> 1;
    const int q = (tid & 1) * 4;
    uint32_t* aH = reinterpret_cast<uint32_t*>(stage);
    uint32_t* aL = reinterpret_cast<uint32_t*>(stage + PL_ELEMS);
    uint32_t* bH = reinterpret_cast<uint32_t*>(stage + 2 * PL_ELEMS);
    uint32_t* bL = reinterpret_cast<uint32_t*>(stage + 3 * PL_ELEMS);
    const int rowU = r * (SSTR / 2);
#pragma unroll
    for (int j = 0; j < 4; j++) {
        int idx = rowU + (q + j) * 2;
        float r0, r1, r2, r3;
        uint32_t h0 = pack_hi(v[j].x, v[j].y, r0, r1);
        uint32_t h1 = pack_hi(v[j].z, v[j].w, r2, r3);
        aH[idx] = h0; aH[idx + 1] = h1;
        aL[idx] = pack2(r0, r1); aL[idx + 1] = pack2(r2, r3);
        uint32_t g0 = pack_hi(v[4 + j].x, v[4 + j].y, r0, r1);
        uint32_t g1 = pack_hi(v[4 + j].z, v[4 + j].w, r2, r3);
        bH[idx] = g0; bH[idx + 1] = g1;
        bL[idx] = pack2(r0, r1); bL[idx + 1] = pack2(r2, r3);
    }
}

// MMA over one resident stage: warp tile 32(M) x 64(N), 3 planes (hh, hl, lh).
__device__ __forceinline__ void mma_stage(uint32_t sb, float (&acc)[2][8][4],
                                          int lane, int wm, int wn) {
    const int g = lane >> 3, l = lane & 7;
#pragma unroll
    for (int k16 = 0; k16 < 2; k16++) {
        uint32_t aH[2][4], aL[2][4];
        const int acol = k16 * 16 + (g >> 1) * 8;
#pragma unroll
        for (int mt = 0; mt < 2; mt++) {
            const int arow = wm + mt * 16 + (g & 1) * 8 + l;
            uint32_t off = (uint32_t)(arow * SSTR + acol) * 2;
            ldsm4(aH[mt], sb + off);
            ldsm4(aL[mt], sb + PL_BYTES + off);
        }
        const int bcol = k16 * 16 + (g & 1) * 8;
#pragma unroll
        for (int np = 0; np < 4; np++) {
            const int brow = wn + np * 16 + (g >> 1) * 8 + l;
            uint32_t off = (uint32_t)(brow * SSTR + bcol) * 2;
            uint32_t bH[4], bL[4];
            ldsm4(bH, sb + 2 * PL_BYTES + off);
            ldsm4(bL, sb + 3 * PL_BYTES + off);
#pragma unroll
            for (int mt = 0; mt < 2; mt++) {
#pragma unroll
                for (int nt = 0; nt < 2; nt++) {
                    float* c = acc[mt][np * 2 + nt];
                    mma16816(c, aH[mt], &bH[nt * 2]);
                    mma16816(c, aH[mt], &bL[nt * 2]);
                    mma16816(c, aL[mt], &bH[nt * 2]);
                }
            }
        }
    }
}

// ---------------------------------------------------------------------------
// GEMM1: g_Bu = U @ W^T + bias
// ---------------------------------------------------------------------------
__global__ __launch_bounds__(256, 1) void k_mm_bu(
    const float* __restrict__ U, const float* __restrict__ W,
    const float* __restrict__ bias)
{
    extern __shared__ __nv_bfloat16 smem[];
    const int tid = threadIdx.x;
    const int bn = blockIdx.x, bm = blockIdx.y;
    const int tileRow = bm * TM;
    const int lane = tid & 31, wid = tid >> 5;
    const int wm = (wid & 3) * 32, wn = (wid >> 2) * 64;
    const uint32_t smb = smem_u32(smem);

    float acc[2][8][4];
#pragma unroll
    for (int a = 0; a < 2; a++)
#pragma unroll
        for (int b = 0; b < 8; b++)
#pragma unroll
            for (int c = 0; c < 4; c++) acc[a][b][c] = 0.0f;

    const float* aBase = U + (size_t)tileRow * kQ;
    const float* bBase = W + (size_t)bn * TN * kQ;

    float4 v[8];
    ldg_chunk(aBase, bBase, tid, v);
    sts_chunk(smem, tid, v);
    __syncthreads();
    for (int c = 0; c < 8; c++) {
        if (c < 7) ldg_chunk(aBase + (c + 1) * BK, bBase + (c + 1) * BK, tid, v);
        mma_stage(smb + (c & 1) * STAGE_BYTES, acc, lane, wm, wn);
        if (c < 7) sts_chunk(smem + ((c + 1) & 1) * STAGE_ELEMS, tid, v);
        __syncthreads();
    }

    const int r0 = tileRow + wm + (lane >> 2);
    const int cb = bn * TN + wn;
#pragma unroll
    for (int mt = 0; mt < 2; mt++) {
        const int rr = r0 + mt * 16;
#pragma unroll
        for (int nt = 0; nt < 8; nt++) {
            const int cc = cb + nt * 8 + (lane & 3) * 2;
            const float b0 = bias[cc], b1 = bias[cc + 1];
            float2 lo, hi;
            lo.x = acc[mt][nt][0] + b0; lo.y = acc[mt][nt][1] + b1;
            hi.x = acc[mt][nt][2] + b0; hi.y = acc[mt][nt][3] + b1;
            *reinterpret_cast<float2*>(&g_Bu[(size_t)rr * kQ + cc]) = lo;
            *reinterpret_cast<float2*>(&g_Bu[(size_t)(rr + 8) * kQ + cc]) = hi;
        }
    }
}

// ---------------------------------------------------------------------------
// GEMM2: h = Y@W_C^T + U@W_D^T + bC + bD; g=gelu(h); out = g*sigmoid(g)+u
// ---------------------------------------------------------------------------
__global__ __launch_bounds__(256, 1) void k_mm_out(
    const float* __restrict__ Y, const float* __restrict__ U,
    const float* __restrict__ WC, const float* __restrict__ WD,
    const float* __restrict__ bC, const float* __restrict__ bD,
    float* __restrict__ Out)
{
    extern __shared__ __nv_bfloat16 smem[];
    const int tid = threadIdx.x;
    const int bn = blockIdx.x, bm = blockIdx.y;
    const int tileRow = bm * TM;
    const int lane = tid & 31, wid = tid >> 5;
    const int wm = (wid & 3) * 32, wn = (wid >> 2) * 64;
    const uint32_t smb = smem_u32(smem);

    float acc[2][8][4];
#pragma unroll
    for (int a = 0; a < 2; a++)
#pragma unroll
        for (int b = 0; b < 8; b++)
#pragma unroll
            for (int c = 0; c < 4; c++) acc[a][b][c] = 0.0f;

    float4 v[8];
    {
        const float* a0 = Y + (size_t)tileRow * kQ;
        const float* b0 = WC + (size_t)bn * TN * kQ;
        ldg_chunk(a0, b0, tid, v);
        sts_chunk(smem, tid, v);
    }
    __syncthreads();
    for (int c = 0; c < 16; c++) {
        if (c < 15) {
            const int n = c + 1;
            const float* aB = (n < 8 ? Y : U) + (size_t)tileRow * kQ + (n & 7) * BK;
            const float* bB = (n < 8 ? WC : WD) + (size_t)bn * TN * kQ + (n & 7) * BK;
            ldg_chunk(aB, bB, tid, v);
        }
        mma_stage(smb + (c & 1) * STAGE_BYTES, acc, lane, wm, wn);
        if (c < 15) sts_chunk(smem + ((c + 1) & 1) * STAGE_ELEMS, tid, v);
        __syncthreads();
    }

    const int r0 = tileRow + wm + (lane >> 2);
    const int cb = bn * TN + wn;
#pragma unroll
    for (int mt = 0; mt < 2; mt++) {
        const int rr = r0 + mt * 16;
#pragma unroll
        for (int nt = 0; nt < 8; nt++) {
            const int cc = cb + nt * 8 + (lane & 3) * 2;
            const float b0 = bC[cc] + bD[cc], b1 = bC[cc + 1] + bD[cc + 1];
#pragma unroll
            for (int half = 0; half < 2; half++) {
                const int row = rr + half * 8;
                float h0 = acc[mt][nt][half * 2 + 0] + b0;
                float h1 = acc[mt][nt][half * 2 + 1] + b1;
                float2 uv = *reinterpret_cast<const float2*>(&U[(size_t)row * kQ + cc]);
                float g0 = 0.5f * h0 * (1.0f + erff(h0 * 0.70710678118654752f));
                float g1 = 0.5f * h1 * (1.0f + erff(h1 * 0.70710678118654752f));
                float o0 = fmaf(g0, 1.0f / (1.0f + expf(-g0)), uv.x);
                float o1 = fmaf(g1, 1.0f / (1.0f + expf(-g1)), uv.y);
                float2 w; w.x = o0; w.y = o1;
                *reinterpret_cast<float2*>(&Out[(size_t)row * kQ + cc]) = w;
            }
        }
    }
}

// ---------------------------------------------------------------------------
// Scan (3-pass chunked), unchanged from R1
// ---------------------------------------------------------------------------
__global__ __launch_bounds__(256) void k_scan_ends(const float* __restrict__ A)
{
    int idx = blockIdx.x * blockDim.x + threadIdx.x;
    int qi = idx & (kQ - 1);
    int c  = (idx >> 8) & (kNChunk - 1);
    int b  = idx >> 13;

    float av  = A[qi];
    float s   = 1.0f / (1.0f + kDT * kDT * av);
    float dts = kDT * s;
    float dsa = dts * av;

    const float* p = g_Bu + ((size_t)(b * kN + c * kCLen)) * kQ + qi;
    float x = 0.0f, z = 0.0f;
#pragma unroll 4
    for (int n = 0; n < kCLen; n++) {
        float bu = p[(size_t)n * kQ];
        float fx = dts * bu;
        float xn = fmaf(s, x, fmaf(-dsa, z, fx));
        float zn = fmaf(dts, x, fmaf(s, z, kDT * fx));
        x = xn; z = zn;
    }
    g_end[idx] = make_float2(x, z);
}

__global__ __launch_bounds__(256) void k_scan_combine(const float* __restrict__ A)
{
    int idx = blockIdx.x * blockDim.x + threadIdx.x;
    int qi = idx & (kQ - 1);
    int b  = idx >> 8;

    float av  = A[qi];
    float s   = 1.0f / (1.0f + kDT * kDT * av);
    float dts = kDT * s;
    float dsa = dts * av;

    float p00 = s, p01 = -dsa, p10 = dts, p11 = s;
#pragma unroll
    for (int i = 0; i < 7; i++) {
        float t   = p00 + p11;
        float bc  = p01 * p10;
        float n00 = fmaf(p00, p00, bc);
        float n01 = p01 * t;
        float n10 = p10 * t;
        float n11 = fmaf(p11, p11, bc);
        p00 = n00; p01 = n01; p10 = n10; p11 = n11;
    }

    float x = 0.0f, z = 0.0f;
    for (int c = 0; c < kNChunk; c++) {
        int gi = (b * kNChunk + c) * kQ + qi;
        g_init[gi] = make_float2(x, z);
        float2 e = g_end[gi];
        float xn = fmaf(p00, x, fmaf(p01, z, e.x));
        float zn = fmaf(p10, x, fmaf(p11, z, e.y));
        x = xn; z = zn;
    }
}

__global__ __launch_bounds__(256) void k_scan_emit(
    const float* __restrict__ A, float* __restrict__ Yout)
{
    int idx = blockIdx.x * blockDim.x + threadIdx.x;
    int qi = idx & (kQ - 1);
    int c  = (idx >> 8) & (kNChunk - 1);
    int b  = idx >> 13;

    float av  = A[qi];
    float s   = 1.0f / (1.0f + kDT * kDT * av);
    float dts = kDT * s;
    float dsa = dts * av;

    size_t off = ((size_t)(b * kN + c * kCLen)) * kQ + qi;
    const float* p = g_Bu + off;
    float* yp = Yout + off;

    float2 st = g_init[idx];
    float x = st.x, z = st.y;
#pragma unroll 4
    for (int n = 0; n < kCLen; n++) {
        float bu = p[(size_t)n * kQ];
        float fx = dts * bu;
        float xn = fmaf(s, x, fmaf(-dsa, z, fx));
        float zn = fmaf(dts, x, fmaf(s, z, kDT * fx));
        x = xn; z = zn;
        yp[(size_t)n * kQ] = z;
    }
}

// ---------------------------------------------------------------------------
// Launch
// ---------------------------------------------------------------------------
extern "C" void kernel_launch(void* const* d_in, const int* in_sizes, int n_in,
                              void* d_out, int out_size)
{
    const float* u  = (const float*)d_in[0];
    const float* a  = (const float*)d_in[1];
    const float* WB = (const float*)d_in[2];
    const float* bB = (const float*)d_in[3];
    const float* WC = (const float*)d_in[4];
    const float* bC = (const float*)d_in[5];
    const float* WD = (const float*)d_in[6];
    const float* bD = (const float*)d_in[7];

    float* out  = (float*)d_out;
    float* yout = out + (size_t)out_size / 2;

    static bool attr_done = false;
    if (!attr_done) {
        cudaFuncSetAttribute(k_mm_bu,  cudaFuncAttributeMaxDynamicSharedMemorySize, SMEM_BYTES);
        cudaFuncSetAttribute(k_mm_out, cudaFuncAttributeMaxDynamicSharedMemorySize, SMEM_BYTES);
        attr_done = true;
    }

    dim3 grid(TN == 128 ? kQ / TN : 1, kM / TM);   // (2, 512)
    k_mm_bu<<<grid, 256, SMEM_BYTES>>>(u, WB, bB);

    int scanThreads = kB * kNChunk * kQ;
    k_scan_ends<<<scanThreads / 256, 256>>>(a);
    k_scan_combine<<<(kB * kQ) / 256, 256>>>(a);
    k_scan_emit<<<scanThreads / 256, 256>>>(a, yout);

    k_mm_out<<<grid, 256, SMEM_BYTES>>>(yout, u, WC, WD, bC, bD, out);
}

// round 4
// speedup vs baseline: 2.0471x; 1.0883x over previous
#include <cuda_runtime.h>
#include <cuda_bf16.h>
#include <cuda_fp16.h>
#include <math.h>
#include <stdint.h>

// ---------------------------------------------------------------------------
// LinOSS layer: B=16, N=4096, q=256 on sm_103
// GEMMs via mma.sync fp16 2-pass (A split hi/lo fp16, B rounded fp16).
//   Bu = u @ W_B^T + b_B
//   y  = IM scan (chunked 3-pass, 64 chunks)
//   h  = y@W_C^T + u@W_D^T + bC + bD; g = gelu(h); out = g*sigmoid(g)+u
// Output: [out | y]
// ---------------------------------------------------------------------------

namespace {
constexpr int kB = 16;
constexpr int kN = 4096;
constexpr int kQ = 256;
constexpr int kM = kB * kN;                 // 65536
constexpr float kDT = 1.0f / 4096.0f;
constexpr int kNChunk = 64;
constexpr int kCLen = kN / kNChunk;         // 64

constexpr int TM = 128, TN = 128, BK = 32;  // CTA tile, K-chunk (fp16 elems)
constexpr int SSTR = 40;                    // smem row stride (fp16), 80B
constexpr int PL_ELEMS = TM * SSTR;         // 5120 fp16
constexpr int PL_BYTES = PL_ELEMS * 2;      // 10240
constexpr int STAGE_ELEMS = 3 * PL_ELEMS;   // aHi, aLo, b
constexpr int STAGE_BYTES = 3 * PL_BYTES;   // 30720
constexpr int SMEM_BYTES = 2 * STAGE_BYTES; // 61440
}  // namespace

// Device scratch (static; no cudaMalloc allowed)
__device__ float  g_Bu[(size_t)kM * kQ];
__device__ float2 g_end[kB * kNChunk * kQ];
__device__ float2 g_init[kB * kNChunk * kQ];

// ---------------------------------------------------------------------------
// helpers
// ---------------------------------------------------------------------------
__device__ __forceinline__ uint32_t smem_u32(const void* p) {
    uint32_t a;
    asm("{ .reg .u64 t; cvta.to.shared.u64 t, %1; cvt.u32.u64 %0, t; }" : "=r"(a) : "l"(p));
    return a;
}
// pack two floats to fp16x2, emit residuals
__device__ __forceinline__ uint32_t packh_hi(float a, float b, float& ra, float& rb) {
    __half2 h = __floats2half2_rn(a, b);
    ra = a - __half2float(__low2half(h));
    rb = b - __half2float(__high2half(h));
    uint32_t u; memcpy(&u, &h, 4); return u;
}
__device__ __forceinline__ uint32_t packh(float a, float b) {
    __half2 h = __floats2half2_rn(a, b);
    uint32_t u; memcpy(&u, &h, 4); return u;
}
__device__ __forceinline__ void ldsm4(uint32_t (&r)[4], uint32_t addr) {
    asm volatile("ldmatrix.sync.aligned.m8n8.x4.shared.b16 {%0,%1,%2,%3}, [%4];"
                 : "=r"(r[0]), "=r"(r[1]), "=r"(r[2]), "=r"(r[3]) : "r"(addr));
}
__device__ __forceinline__ void mma16816(float* c, const uint32_t* a, const uint32_t* b) {
    asm volatile(
        "mma.sync.aligned.m16n8k16.row.col.f32.f16.f16.f32 "
        "{%0,%1,%2,%3}, {%4,%5,%6,%7}, {%8,%9}, {%0,%1,%2,%3};"
        : "+f"(c[0]), "+f"(c[1]), "+f"(c[2]), "+f"(c[3])
        : "r"(a[0]), "r"(a[1]), "r"(a[2]), "r"(a[3]), "r"(b[0]), "r"(b[1]));
}

// Global fp32 load of one K-chunk: A rows 0..127, B rows 0..127.
// 256 threads: thread t -> row t/2, float4 slots (t&1)*4 .. +3.
__device__ __forceinline__ void ldg_chunk(const float* __restrict__ aSrc,
                                          const float* __restrict__ bSrc,
                                          int tid, float4 (&v)[8]) {
    const int r = tid >> 1;
    const int q = (tid & 1) * 4;
    const float4* ap = reinterpret_cast<const float4*>(aSrc + (size_t)r * kQ) + q;
    const float4* bp = reinterpret_cast<const float4*>(bSrc + (size_t)r * kQ) + q;
#pragma unroll
    for (int j = 0; j < 4; j++) { v[j] = ap[j]; v[4 + j] = bp[j]; }
}

// A: split hi/lo fp16 planes; B: rounded fp16 plane.
__device__ __forceinline__ void sts_chunk(__half* stage, int tid, const float4 (&v)[8]) {
    const int r = tid >> 1;
    const int q = (tid & 1) * 4;
    uint32_t* aH = reinterpret_cast<uint32_t*>(stage);
    uint32_t* aL = reinterpret_cast<uint32_t*>(stage + PL_ELEMS);
    uint32_t* bP = reinterpret_cast<uint32_t*>(stage + 2 * PL_ELEMS);
    const int rowU = r * (SSTR / 2);
#pragma unroll
    for (int j = 0; j < 4; j++) {
        int idx = rowU + (q + j) * 2;
        float r0, r1, r2, r3;
        uint32_t h0 = packh_hi(v[j].x, v[j].y, r0, r1);
        uint32_t h1 = packh_hi(v[j].z, v[j].w, r2, r3);
        aH[idx] = h0; aH[idx + 1] = h1;
        aL[idx] = packh(r0, r1); aL[idx + 1] = packh(r2, r3);
        bP[idx] = packh(v[4 + j].x, v[4 + j].y);
        bP[idx + 1] = packh(v[4 + j].z, v[4 + j].w);
    }
}

// MMA over one resident stage: warp tile 32(M) x 64(N), 2 passes (hi, lo).
__device__ __forceinline__ void mma_stage(uint32_t sb, float (&acc)[2][8][4],
                                          int lane, int wm, int wn) {
    const int g = lane >> 3, l = lane & 7;
#pragma unroll
    for (int k16 = 0; k16 < 2; k16++) {
        uint32_t aH[2][4], aL[2][4];
        const int acol = k16 * 16 + (g >> 1) * 8;
#pragma unroll
        for (int mt = 0; mt < 2; mt++) {
            const int arow = wm + mt * 16 + (g & 1) * 8 + l;
            uint32_t off = (uint32_t)(arow * SSTR + acol) * 2;
            ldsm4(aH[mt], sb + off);
            ldsm4(aL[mt], sb + PL_BYTES + off);
        }
        const int bcol = k16 * 16 + (g & 1) * 8;
#pragma unroll
        for (int np = 0; np < 4; np++) {
            const int brow = wn + np * 16 + (g >> 1) * 8 + l;
            uint32_t bfrag[4];
            ldsm4(bfrag, sb + 2 * PL_BYTES + (uint32_t)(brow * SSTR + bcol) * 2);
#pragma unroll
            for (int mt = 0; mt < 2; mt++) {
#pragma unroll
                for (int nt = 0; nt < 2; nt++) {
                    float* c = acc[mt][np * 2 + nt];
                    mma16816(c, aH[mt], &bfrag[nt * 2]);
                    mma16816(c, aL[mt], &bfrag[nt * 2]);
                }
            }
        }
    }
}

// ---------------------------------------------------------------------------
// GEMM1: g_Bu = U @ W^T + bias
// ---------------------------------------------------------------------------
__global__ __launch_bounds__(256, 1) void k_mm_bu(
    const float* __restrict__ U, const float* __restrict__ W,
    const float* __restrict__ bias)
{
    extern __shared__ __half smem[];
    const int tid = threadIdx.x;
    const int bn = blockIdx.x, bm = blockIdx.y;
    const int tileRow = bm * TM;
    const int lane = tid & 31, wid = tid >> 5;
    const int wm = (wid & 3) * 32, wn = (wid >> 2) * 64;
    const uint32_t smb = smem_u32(smem);

    float acc[2][8][4];
#pragma unroll
    for (int a = 0; a < 2; a++)
#pragma unroll
        for (int b = 0; b < 8; b++)
#pragma unroll
            for (int c = 0; c < 4; c++) acc[a][b][c] = 0.0f;

    const float* aBase = U + (size_t)tileRow * kQ;
    const float* bBase = W + (size_t)bn * TN * kQ;

    float4 v[8];
    ldg_chunk(aBase, bBase, tid, v);
    sts_chunk(smem, tid, v);
    __syncthreads();
    for (int c = 0; c < 8; c++) {
        if (c < 7) ldg_chunk(aBase + (c + 1) * BK, bBase + (c + 1) * BK, tid, v);
        mma_stage(smb + (c & 1) * STAGE_BYTES, acc, lane, wm, wn);
        if (c < 7) sts_chunk(smem + ((c + 1) & 1) * STAGE_ELEMS, tid, v);
        __syncthreads();
    }

    const int r0 = tileRow + wm + (lane >> 2);
    const int cb = bn * TN + wn;
#pragma unroll
    for (int mt = 0; mt < 2; mt++) {
        const int rr = r0 + mt * 16;
#pragma unroll
        for (int nt = 0; nt < 8; nt++) {
            const int cc = cb + nt * 8 + (lane & 3) * 2;
            const float b0 = bias[cc], b1 = bias[cc + 1];
            float2 lo, hi;
            lo.x = acc[mt][nt][0] + b0; lo.y = acc[mt][nt][1] + b1;
            hi.x = acc[mt][nt][2] + b0; hi.y = acc[mt][nt][3] + b1;
            *reinterpret_cast<float2*>(&g_Bu[(size_t)rr * kQ + cc]) = lo;
            *reinterpret_cast<float2*>(&g_Bu[(size_t)(rr + 8) * kQ + cc]) = hi;
        }
    }
}

// ---------------------------------------------------------------------------
// GEMM2: h = Y@W_C^T + U@W_D^T + bC + bD; g=gelu(h); out = g*sigmoid(g)+u
// ---------------------------------------------------------------------------
__global__ __launch_bounds__(256, 1) void k_mm_out(
    const float* __restrict__ Y, const float* __restrict__ U,
    const float* __restrict__ WC, const float* __restrict__ WD,
    const float* __restrict__ bC, const float* __restrict__ bD,
    float* __restrict__ Out)
{
    extern __shared__ __half smem[];
    const int tid = threadIdx.x;
    const int bn = blockIdx.x, bm = blockIdx.y;
    const int tileRow = bm * TM;
    const int lane = tid & 31, wid = tid >> 5;
    const int wm = (wid & 3) * 32, wn = (wid >> 2) * 64;
    const uint32_t smb = smem_u32(smem);

    float acc[2][8][4];
#pragma unroll
    for (int a = 0; a < 2; a++)
#pragma unroll
        for (int b = 0; b < 8; b++)
#pragma unroll
            for (int c = 0; c < 4; c++) acc[a][b][c] = 0.0f;

    float4 v[8];
    {
        const float* a0 = Y + (size_t)tileRow * kQ;
        const float* b0 = WC + (size_t)bn * TN * kQ;
        ldg_chunk(a0, b0, tid, v);
        sts_chunk(smem, tid, v);
    }
    __syncthreads();
    for (int c = 0; c < 16; c++) {
        if (c < 15) {
            const int n = c + 1;
            const float* aB = (n < 8 ? Y : U) + (size_t)tileRow * kQ + (n & 7) * BK;
            const float* bB = (n < 8 ? WC : WD) + (size_t)bn * TN * kQ + (n & 7) * BK;
            ldg_chunk(aB, bB, tid, v);
        }
        mma_stage(smb + (c & 1) * STAGE_BYTES, acc, lane, wm, wn);
        if (c < 15) sts_chunk(smem + ((c + 1) & 1) * STAGE_ELEMS, tid, v);
        __syncthreads();
    }

    const int r0 = tileRow + wm + (lane >> 2);
    const int cb = bn * TN + wn;
#pragma unroll
    for (int mt = 0; mt < 2; mt++) {
        const int rr = r0 + mt * 16;
#pragma unroll
        for (int nt = 0; nt < 8; nt++) {
            const int cc = cb + nt * 8 + (lane & 3) * 2;
            const float b0 = bC[cc] + bD[cc], b1 = bC[cc + 1] + bD[cc + 1];
#pragma unroll
            for (int half = 0; half < 2; half++) {
                const int row = rr + half * 8;
                float h0 = acc[mt][nt][half * 2 + 0] + b0;
                float h1 = acc[mt][nt][half * 2 + 1] + b1;
                float2 uv = *reinterpret_cast<const float2*>(&U[(size_t)row * kQ + cc]);
                float g0 = 0.5f * h0 * (1.0f + erff(h0 * 0.70710678118654752f));
                float g1 = 0.5f * h1 * (1.0f + erff(h1 * 0.70710678118654752f));
                float o0 = fmaf(g0, 1.0f / (1.0f + expf(-g0)), uv.x);
                float o1 = fmaf(g1, 1.0f / (1.0f + expf(-g1)), uv.y);
                float2 w; w.x = o0; w.y = o1;
                *reinterpret_cast<float2*>(&Out[(size_t)row * kQ + cc]) = w;
            }
        }
    }
}

// ---------------------------------------------------------------------------
// Scan (3-pass chunked, 64 chunks of 64)
// ---------------------------------------------------------------------------
__global__ __launch_bounds__(256) void k_scan_ends(const float* __restrict__ A)
{
    int idx = blockIdx.x * blockDim.x + threadIdx.x;   // < kB*kNChunk*kQ
    int qi = idx & (kQ - 1);
    int c  = (idx >> 8) & (kNChunk - 1);
    int b  = idx >> 14;

    float av  = A[qi];
    float s   = 1.0f / (1.0f + kDT * kDT * av);
    float dts = kDT * s;
    float dsa = dts * av;

    const float* p = g_Bu + ((size_t)(b * kN + c * kCLen)) * kQ + qi;
    float x = 0.0f, z = 0.0f;
#pragma unroll 4
    for (int n = 0; n < kCLen; n++) {
        float bu = p[(size_t)n * kQ];
        float fx = dts * bu;
        float xn = fmaf(s, x, fmaf(-dsa, z, fx));
        float zn = fmaf(dts, x, fmaf(s, z, kDT * fx));
        x = xn; z = zn;
    }
    g_end[idx] = make_float2(x, z);
}

__global__ __launch_bounds__(256) void k_scan_combine(const float* __restrict__ A)
{
    int idx = blockIdx.x * blockDim.x + threadIdx.x;  // < kB*kQ
    int qi = idx & (kQ - 1);
    int b  = idx >> 8;

    float av  = A[qi];
    float s   = 1.0f / (1.0f + kDT * kDT * av);
    float dts = kDT * s;
    float dsa = dts * av;

    float p00 = s, p01 = -dsa, p10 = dts, p11 = s;
#pragma unroll
    for (int i = 0; i < 6; i++) {          // M^(2^6) = M^kCLen
        float t   = p00 + p11;
        float bc  = p01 * p10;
        float n00 = fmaf(p00, p00, bc);
        float n01 = p01 * t;
        float n10 = p10 * t;
        float n11 = fmaf(p11, p11, bc);
        p00 = n00; p01 = n01; p10 = n10; p11 = n11;
    }

    float x = 0.0f, z = 0.0f;
#pragma unroll 8
    for (int c = 0; c < kNChunk; c++) {
        int gi = (b * kNChunk + c) * kQ + qi;
        g_init[gi] = make_float2(x, z);
        float2 e = g_end[gi];
        float xn = fmaf(p00, x, fmaf(p01, z, e.x));
        float zn = fmaf(p10, x, fmaf(p11, z, e.y));
        x = xn; z = zn;
    }
}

__global__ __launch_bounds__(256) void k_scan_emit(
    const float* __restrict__ A, float* __restrict__ Yout)
{
    int idx = blockIdx.x * blockDim.x + threadIdx.x;
    int qi = idx & (kQ - 1);
    int c  = (idx >> 8) & (kNChunk - 1);
    int b  = idx >> 14;

    float av  = A[qi];
    float s   = 1.0f / (1.0f + kDT * kDT * av);
    float dts = kDT * s;
    float dsa = dts * av;

    size_t off = ((size_t)(b * kN + c * kCLen)) * kQ + qi;
    const float* p = g_Bu + off;
    float* yp = Yout + off;

    float2 st = g_init[idx];
    float x = st.x, z = st.y;
#pragma unroll 4
    for (int n = 0; n < kCLen; n++) {
        float bu = p[(size_t)n * kQ];
        float fx = dts * bu;
        float xn = fmaf(s, x, fmaf(-dsa, z, fx));
        float zn = fmaf(dts, x, fmaf(s, z, kDT * fx));
        x = xn; z = zn;
        yp[(size_t)n * kQ] = z;
    }
}

// ---------------------------------------------------------------------------
// Launch
// ---------------------------------------------------------------------------
extern "C" void kernel_launch(void* const* d_in, const int* in_sizes, int n_in,
                              void* d_out, int out_size)
{
    const float* u  = (const float*)d_in[0];
    const float* a  = (const float*)d_in[1];
    const float* WB = (const float*)d_in[2];
    const float* bB = (const float*)d_in[3];
    const float* WC = (const float*)d_in[4];
    const float* bC = (const float*)d_in[5];
    const float* WD = (const float*)d_in[6];
    const float* bD = (const float*)d_in[7];

    float* out  = (float*)d_out;
    float* yout = out + (size_t)out_size / 2;

    static bool attr_done = false;
    if (!attr_done) {
        cudaFuncSetAttribute(k_mm_bu,  cudaFuncAttributeMaxDynamicSharedMemorySize, SMEM_BYTES);
        cudaFuncSetAttribute(k_mm_out, cudaFuncAttributeMaxDynamicSharedMemorySize, SMEM_BYTES);
        attr_done = true;
    }

    dim3 grid(kQ / TN, kM / TM);                // (2, 512)
    k_mm_bu<<<grid, 256, SMEM_BYTES>>>(u, WB, bB);

    int scanThreads = kB * kNChunk * kQ;        // 262144
    k_scan_ends<<<scanThreads / 256, 256>>>(a);
    k_scan_combine<<<(kB * kQ) / 256, 256>>>(a);
    k_scan_emit<<<scanThreads / 256, 256>>>(a, yout);

    k_mm_out<<<grid, 256, SMEM_BYTES>>>(yout, u, WC, WD, bC, bD, out);
}

// round 5
// speedup vs baseline: 2.7176x; 1.3275x over previous
#include <cuda_runtime.h>
#include <cuda_bf16.h>
#include <cuda_fp16.h>
#include <math.h>
#include <stdint.h>

// ---------------------------------------------------------------------------
// LinOSS layer: B=16, N=4096, q=256 on sm_103
// GEMMs via mma.sync fp16 single-pass (A, B rounded to fp16, fp32 accum).
//   Bu = u @ W_B^T + b_B
//   y  = IM scan (chunked 3-pass, 64 chunks)
//   h  = y@W_C^T + u@W_D^T + bC + bD; g = gelu(h); out = g*sigmoid(g)+u
// Output: [out | y]
// ---------------------------------------------------------------------------

namespace {
constexpr int kB = 16;
constexpr int kN = 4096;
constexpr int kQ = 256;
constexpr int kM = kB * kN;                 // 65536
constexpr float kDT = 1.0f / 4096.0f;
constexpr int kNChunk = 64;
constexpr int kCLen = kN / kNChunk;         // 64

constexpr int TM = 128, TN = 128, BK = 32;  // CTA tile, K-chunk (fp16 elems)
constexpr int SSTR = 40;                    // smem row stride (fp16), 80B
constexpr int PL_ELEMS = TM * SSTR;         // 5120 fp16
constexpr int PL_BYTES = PL_ELEMS * 2;      // 10240
constexpr int STAGE_ELEMS = 2 * PL_ELEMS;   // a, b
constexpr int STAGE_BYTES = 2 * PL_BYTES;   // 20480
constexpr int SMEM_BYTES = 2 * STAGE_BYTES; // 40960
}  // namespace

// Device scratch (static; no cudaMalloc allowed)
__device__ float  g_Bu[(size_t)kM * kQ];
__device__ float2 g_end[kB * kNChunk * kQ];
__device__ float2 g_init[kB * kNChunk * kQ];

// ---------------------------------------------------------------------------
// helpers
// ---------------------------------------------------------------------------
__device__ __forceinline__ uint32_t smem_u32(const void* p) {
    uint32_t a;
    asm("{ .reg .u64 t; cvta.to.shared.u64 t, %1; cvt.u32.u64 %0, t; }" : "=r"(a) : "l"(p));
    return a;
}
__device__ __forceinline__ uint32_t packh(float a, float b) {
    __half2 h = __floats2half2_rn(a, b);
    uint32_t u; memcpy(&u, &h, 4); return u;
}
__device__ __forceinline__ void ldsm4(uint32_t (&r)[4], uint32_t addr) {
    asm volatile("ldmatrix.sync.aligned.m8n8.x4.shared.b16 {%0,%1,%2,%3}, [%4];"
                 : "=r"(r[0]), "=r"(r[1]), "=r"(r[2]), "=r"(r[3]) : "r"(addr));
}
__device__ __forceinline__ void mma16816(float* c, const uint32_t* a, const uint32_t* b) {
    asm volatile(
        "mma.sync.aligned.m16n8k16.row.col.f32.f16.f16.f32 "
        "{%0,%1,%2,%3}, {%4,%5,%6,%7}, {%8,%9}, {%0,%1,%2,%3};"
        : "+f"(c[0]), "+f"(c[1]), "+f"(c[2]), "+f"(c[3])
        : "r"(a[0]), "r"(a[1]), "r"(a[2]), "r"(a[3]), "r"(b[0]), "r"(b[1]));
}

// Global fp32 load of one K-chunk: A rows 0..127, B rows 0..127.
// 256 threads: thread t -> row t/2, float4 slots (t&1)*4 .. +3.
__device__ __forceinline__ void ldg_chunk(const float* __restrict__ aSrc,
                                          const float* __restrict__ bSrc,
                                          int tid, float4 (&v)[8]) {
    const int r = tid >> 1;
    const int q = (tid & 1) * 4;
    const float4* ap = reinterpret_cast<const float4*>(aSrc + (size_t)r * kQ) + q;
    const float4* bp = reinterpret_cast<const float4*>(bSrc + (size_t)r * kQ) + q;
#pragma unroll
    for (int j = 0; j < 4; j++) { v[j] = ap[j]; v[4 + j] = bp[j]; }
}

// Round both operands to fp16 planes.
__device__ __forceinline__ void sts_chunk(__half* stage, int tid, const float4 (&v)[8]) {
    const int r = tid >> 1;
    const int q = (tid & 1) * 4;
    uint32_t* aP = reinterpret_cast<uint32_t*>(stage);
    uint32_t* bP = reinterpret_cast<uint32_t*>(stage + PL_ELEMS);
    const int rowU = r * (SSTR / 2);
#pragma unroll
    for (int j = 0; j < 4; j++) {
        int idx = rowU + (q + j) * 2;
        aP[idx]     = packh(v[j].x, v[j].y);
        aP[idx + 1] = packh(v[j].z, v[j].w);
        bP[idx]     = packh(v[4 + j].x, v[4 + j].y);
        bP[idx + 1] = packh(v[4 + j].z, v[4 + j].w);
    }
}

// MMA over one resident stage: warp tile 32(M) x 64(N), single pass.
__device__ __forceinline__ void mma_stage(uint32_t sb, float (&acc)[2][8][4],
                                          int lane, int wm, int wn) {
    const int g = lane >> 3, l = lane & 7;
#pragma unroll
    for (int k16 = 0; k16 < 2; k16++) {
        uint32_t afrag[2][4];
        const int acol = k16 * 16 + (g >> 1) * 8;
#pragma unroll
        for (int mt = 0; mt < 2; mt++) {
            const int arow = wm + mt * 16 + (g & 1) * 8 + l;
            ldsm4(afrag[mt], sb + (uint32_t)(arow * SSTR + acol) * 2);
        }
        const int bcol = k16 * 16 + (g & 1) * 8;
#pragma unroll
        for (int np = 0; np < 4; np++) {
            const int brow = wn + np * 16 + (g >> 1) * 8 + l;
            uint32_t bfrag[4];
            ldsm4(bfrag, sb + PL_BYTES + (uint32_t)(brow * SSTR + bcol) * 2);
#pragma unroll
            for (int mt = 0; mt < 2; mt++) {
#pragma unroll
                for (int nt = 0; nt < 2; nt++) {
                    mma16816(acc[mt][np * 2 + nt], afrag[mt], &bfrag[nt * 2]);
                }
            }
        }
    }
}

// ---------------------------------------------------------------------------
// GEMM1: g_Bu = U @ W^T + bias
// ---------------------------------------------------------------------------
__global__ __launch_bounds__(256, 2) void k_mm_bu(
    const float* __restrict__ U, const float* __restrict__ W,
    const float* __restrict__ bias)
{
    extern __shared__ __half smem[];
    const int tid = threadIdx.x;
    const int bn = blockIdx.x, bm = blockIdx.y;
    const int tileRow = bm * TM;
    const int lane = tid & 31, wid = tid >> 5;
    const int wm = (wid & 3) * 32, wn = (wid >> 2) * 64;
    const uint32_t smb = smem_u32(smem);

    float acc[2][8][4];
#pragma unroll
    for (int a = 0; a < 2; a++)
#pragma unroll
        for (int b = 0; b < 8; b++)
#pragma unroll
            for (int c = 0; c < 4; c++) acc[a][b][c] = 0.0f;

    const float* aBase = U + (size_t)tileRow * kQ;
    const float* bBase = W + (size_t)bn * TN * kQ;

    float4 v[8];
    ldg_chunk(aBase, bBase, tid, v);
    sts_chunk(smem, tid, v);
    __syncthreads();
    for (int c = 0; c < 8; c++) {
        if (c < 7) ldg_chunk(aBase + (c + 1) * BK, bBase + (c + 1) * BK, tid, v);
        mma_stage(smb + (c & 1) * STAGE_BYTES, acc, lane, wm, wn);
        if (c < 7) sts_chunk(smem + ((c + 1) & 1) * STAGE_ELEMS, tid, v);
        __syncthreads();
    }

    const int r0 = tileRow + wm + (lane >> 2);
    const int cb = bn * TN + wn;
#pragma unroll
    for (int mt = 0; mt < 2; mt++) {
        const int rr = r0 + mt * 16;
#pragma unroll
        for (int nt = 0; nt < 8; nt++) {
            const int cc = cb + nt * 8 + (lane & 3) * 2;
            const float b0 = bias[cc], b1 = bias[cc + 1];
            float2 lo, hi;
            lo.x = acc[mt][nt][0] + b0; lo.y = acc[mt][nt][1] + b1;
            hi.x = acc[mt][nt][2] + b0; hi.y = acc[mt][nt][3] + b1;
            *reinterpret_cast<float2*>(&g_Bu[(size_t)rr * kQ + cc]) = lo;
            *reinterpret_cast<float2*>(&g_Bu[(size_t)(rr + 8) * kQ + cc]) = hi;
        }
    }
}

// ---------------------------------------------------------------------------
// GEMM2: h = Y@W_C^T + U@W_D^T + bC + bD; g=gelu(h); out = g*sigmoid(g)+u
// ---------------------------------------------------------------------------
__global__ __launch_bounds__(256, 2) void k_mm_out(
    const float* __restrict__ Y, const float* __restrict__ U,
    const float* __restrict__ WC, const float* __restrict__ WD,
    const float* __restrict__ bC, const float* __restrict__ bD,
    float* __restrict__ Out)
{
    extern __shared__ __half smem[];
    const int tid = threadIdx.x;
    const int bn = blockIdx.x, bm = blockIdx.y;
    const int tileRow = bm * TM;
    const int lane = tid & 31, wid = tid >> 5;
    const int wm = (wid & 3) * 32, wn = (wid >> 2) * 64;
    const uint32_t smb = smem_u32(smem);

    float acc[2][8][4];
#pragma unroll
    for (int a = 0; a < 2; a++)
#pragma unroll
        for (int b = 0; b < 8; b++)
#pragma unroll
            for (int c = 0; c < 4; c++) acc[a][b][c] = 0.0f;

    float4 v[8];
    {
        const float* a0 = Y + (size_t)tileRow * kQ;
        const float* b0 = WC + (size_t)bn * TN * kQ;
        ldg_chunk(a0, b0, tid, v);
        sts_chunk(smem, tid, v);
    }
    __syncthreads();
    for (int c = 0; c < 16; c++) {
        if (c < 15) {
            const int n = c + 1;
            const float* aB = (n < 8 ? Y : U) + (size_t)tileRow * kQ + (n & 7) * BK;
            const float* bB = (n < 8 ? WC : WD) + (size_t)bn * TN * kQ + (n & 7) * BK;
            ldg_chunk(aB, bB, tid, v);
        }
        mma_stage(smb + (c & 1) * STAGE_BYTES, acc, lane, wm, wn);
        if (c < 15) sts_chunk(smem + ((c + 1) & 1) * STAGE_ELEMS, tid, v);
        __syncthreads();
    }

    const int r0 = tileRow + wm + (lane >> 2);
    const int cb = bn * TN + wn;
#pragma unroll
    for (int mt = 0; mt < 2; mt++) {
        const int rr = r0 + mt * 16;
#pragma unroll
        for (int nt = 0; nt < 8; nt++) {
            const int cc = cb + nt * 8 + (lane & 3) * 2;
            const float b0 = bC[cc] + bD[cc], b1 = bC[cc + 1] + bD[cc + 1];
#pragma unroll
            for (int half = 0; half < 2; half++) {
                const int row = rr + half * 8;
                float h0 = acc[mt][nt][half * 2 + 0] + b0;
                float h1 = acc[mt][nt][half * 2 + 1] + b1;
                float2 uv = *reinterpret_cast<const float2*>(&U[(size_t)row * kQ + cc]);
                float g0 = 0.5f * h0 * (1.0f + erff(h0 * 0.70710678118654752f));
                float g1 = 0.5f * h1 * (1.0f + erff(h1 * 0.70710678118654752f));
                float o0 = fmaf(g0, 1.0f / (1.0f + expf(-g0)), uv.x);
                float o1 = fmaf(g1, 1.0f / (1.0f + expf(-g1)), uv.y);
                float2 w; w.x = o0; w.y = o1;
                *reinterpret_cast<float2*>(&Out[(size_t)row * kQ + cc]) = w;
            }
        }
    }
}

// ---------------------------------------------------------------------------
// Scan (3-pass chunked, 64 chunks of 64)
// ---------------------------------------------------------------------------
__global__ __launch_bounds__(256) void k_scan_ends(const float* __restrict__ A)
{
    int idx = blockIdx.x * blockDim.x + threadIdx.x;   // < kB*kNChunk*kQ
    int qi = idx & (kQ - 1);
    int c  = (idx >> 8) & (kNChunk - 1);
    int b  = idx >> 14;

    float av  = A[qi];
    float s   = 1.0f / (1.0f + kDT * kDT * av);
    float dts = kDT * s;
    float dsa = dts * av;

    const float* p = g_Bu + ((size_t)(b * kN + c * kCLen)) * kQ + qi;
    float x = 0.0f, z = 0.0f;
#pragma unroll 4
    for (int n = 0; n < kCLen; n++) {
        float bu = p[(size_t)n * kQ];
        float fx = dts * bu;
        float xn = fmaf(s, x, fmaf(-dsa, z, fx));
        float zn = fmaf(dts, x, fmaf(s, z, kDT * fx));
        x = xn; z = zn;
    }
    g_end[idx] = make_float2(x, z);
}

__global__ __launch_bounds__(256) void k_scan_combine(const float* __restrict__ A)
{
    int idx = blockIdx.x * blockDim.x + threadIdx.x;  // < kB*kQ
    int qi = idx & (kQ - 1);
    int b  = idx >> 8;

    float av  = A[qi];
    float s   = 1.0f / (1.0f + kDT * kDT * av);
    float dts = kDT * s;
    float dsa = dts * av;

    float p00 = s, p01 = -dsa, p10 = dts, p11 = s;
#pragma unroll
    for (int i = 0; i < 6; i++) {          // M^(2^6) = M^kCLen
        float t   = p00 + p11;
        float bc  = p01 * p10;
        float n00 = fmaf(p00, p00, bc);
        float n01 = p01 * t;
        float n10 = p10 * t;
        float n11 = fmaf(p11, p11, bc);
        p00 = n00; p01 = n01; p10 = n10; p11 = n11;
    }

    float x = 0.0f, z = 0.0f;
#pragma unroll 8
    for (int c = 0; c < kNChunk; c++) {
        int gi = (b * kNChunk + c) * kQ + qi;
        g_init[gi] = make_float2(x, z);
        float2 e = g_end[gi];
        float xn = fmaf(p00, x, fmaf(p01, z, e.x));
        float zn = fmaf(p10, x, fmaf(p11, z, e.y));
        x = xn; z = zn;
    }
}

__global__ __launch_bounds__(256) void k_scan_emit(
    const float* __restrict__ A, float* __restrict__ Yout)
{
    int idx = blockIdx.x * blockDim.x + threadIdx.x;
    int qi = idx & (kQ - 1);
    int c  = (idx >> 8) & (kNChunk - 1);
    int b  = idx >> 14;

    float av  = A[qi];
    float s   = 1.0f / (1.0f + kDT * kDT * av);
    float dts = kDT * s;
    float dsa = dts * av;

    size_t off = ((size_t)(b * kN + c * kCLen)) * kQ + qi;
    const float* p = g_Bu + off;
    float* yp = Yout + off;

    float2 st = g_init[idx];
    float x = st.x, z = st.y;
#pragma unroll 4
    for (int n = 0; n < kCLen; n++) {
        float bu = p[(size_t)n * kQ];
        float fx = dts * bu;
        float xn = fmaf(s, x, fmaf(-dsa, z, fx));
        float zn = fmaf(dts, x, fmaf(s, z, kDT * fx));
        x = xn; z = zn;
        yp[(size_t)n * kQ] = z;
    }
}

// ---------------------------------------------------------------------------
// Launch
// ---------------------------------------------------------------------------
extern "C" void kernel_launch(void* const* d_in, const int* in_sizes, int n_in,
                              void* d_out, int out_size)
{
    const float* u  = (const float*)d_in[0];
    const float* a  = (const float*)d_in[1];
    const float* WB = (const float*)d_in[2];
    const float* bB = (const float*)d_in[3];
    const float* WC = (const float*)d_in[4];
    const float* bC = (const float*)d_in[5];
    const float* WD = (const float*)d_in[6];
    const float* bD = (const float*)d_in[7];

    float* out  = (float*)d_out;
    float* yout = out + (size_t)out_size / 2;

    static bool attr_done = false;
    if (!attr_done) {
        cudaFuncSetAttribute(k_mm_bu,  cudaFuncAttributeMaxDynamicSharedMemorySize, SMEM_BYTES);
        cudaFuncSetAttribute(k_mm_out, cudaFuncAttributeMaxDynamicSharedMemorySize, SMEM_BYTES);
        attr_done = true;
    }

    dim3 grid(kQ / TN, kM / TM);                // (2, 512)
    k_mm_bu<<<grid, 256, SMEM_BYTES>>>(u, WB, bB);

    int scanThreads = kB * kNChunk * kQ;        // 262144
    k_scan_ends<<<scanThreads / 256, 256>>>(a);
    k_scan_combine<<<(kB * kQ) / 256, 256>>>(a);
    k_scan_emit<<<scanThreads / 256, 256>>>(a, yout);

    k_mm_out<<<grid, 256, SMEM_BYTES>>>(yout, u, WC, WD, bC, bD, out);
}

// round 6
// speedup vs baseline: 3.3554x; 1.2347x over previous
#include <cuda_runtime.h>
#include <cuda_fp16.h>
#include <math.h>
#include <stdint.h>

// ---------------------------------------------------------------------------
// LinOSS layer: B=16, N=4096, q=256 on sm_103
// fp16 operands pre-converted once; GEMMs are cp.async 3-stage HMMA pipelines.
//   u16 = fp16(u); W*16 = fp16(W*)
//   Bu  = u16 @ WB16^T + bB                 (fp32 accum)
//   y   = IM scan (chunked 3-pass); also emits y16 = fp16(y)
//   h   = y16@WC16^T + u16@WD16^T + bC + bD; g = gelu(h); out = g*sigmoid(g)+u
// Output: [out | y]
// ---------------------------------------------------------------------------

namespace {
constexpr int kB = 16;
constexpr int kN = 4096;
constexpr int kQ = 256;
constexpr int kM = kB * kN;                 // 65536
constexpr float kDT = 1.0f / 4096.0f;
constexpr int kNChunk = 64;
constexpr int kCLen = kN / kNChunk;         // 64

constexpr int TM = 128, TN = 128, BK = 32;  // CTA tile, K-chunk (fp16)
constexpr int SSTR = 40;                    // smem row stride in halves (80 B)
constexpr int PL_ELEMS = TM * SSTR;         // 5120
constexpr int PL_BYTES = PL_ELEMS * 2;      // 10240
constexpr int STAGE_BYTES = 2 * PL_BYTES;   // 20480 (A plane + B plane)
constexpr int NSTAGE = 3;
constexpr int SMEM_BYTES = NSTAGE * STAGE_BYTES;  // 61440
}  // namespace

// Device scratch (static; no cudaMalloc allowed)
__device__ float  g_Bu[(size_t)kM * kQ];
__device__ float2 g_end[kB * kNChunk * kQ];
__device__ float2 g_init[kB * kNChunk * kQ];
__device__ __half g_u16[(size_t)kM * kQ];
__device__ __half g_y16[(size_t)kM * kQ];
__device__ __half g_WB16[kQ * kQ];
__device__ __half g_WC16[kQ * kQ];
__device__ __half g_WD16[kQ * kQ];

// ---------------------------------------------------------------------------
// helpers
// ---------------------------------------------------------------------------
__device__ __forceinline__ uint32_t smem_u32(const void* p) {
    uint32_t a;
    asm("{ .reg .u64 t; cvta.to.shared.u64 t, %1; cvt.u32.u64 %0, t; }" : "=r"(a) : "l"(p));
    return a;
}
__device__ __forceinline__ uint32_t packh(float a, float b) {
    __half2 h = __floats2half2_rn(a, b);
    uint32_t u; memcpy(&u, &h, 4); return u;
}
__device__ __forceinline__ void ldsm4(uint32_t (&r)[4], uint32_t addr) {
    asm volatile("ldmatrix.sync.aligned.m8n8.x4.shared.b16 {%0,%1,%2,%3}, [%4];"
                 : "=r"(r[0]), "=r"(r[1]), "=r"(r[2]), "=r"(r[3]) : "r"(addr));
}
__device__ __forceinline__ void mma16816(float* c, const uint32_t* a, const uint32_t* b) {
    asm volatile(
        "mma.sync.aligned.m16n8k16.row.col.f32.f16.f16.f32 "
        "{%0,%1,%2,%3}, {%4,%5,%6,%7}, {%8,%9}, {%0,%1,%2,%3};"
        : "+f"(c[0]), "+f"(c[1]), "+f"(c[2]), "+f"(c[3])
        : "r"(a[0]), "r"(a[1]), "r"(a[2]), "r"(a[3]), "r"(b[0]), "r"(b[1]));
}
#define CP_COMMIT() asm volatile("cp.async.commit_group;" ::: "memory")
#define CP_WAIT1()  asm volatile("cp.async.wait_group 1;" ::: "memory")

// Issue one stage: A tile rows 0..127 (cols BK fp16) + B tile rows 0..127.
// 1024 x 16B transfers, 4 per thread.
__device__ __forceinline__ void cpa_stage(uint32_t sb, const __half* __restrict__ aSrc,
                                          const __half* __restrict__ bSrc, int tid) {
#pragma unroll
    for (int k = 0; k < 2; k++) {
        int t = tid + k * 256;             // 0..511
        int r = t >> 2, j = t & 3;
        const __half* g = aSrc + (size_t)r * kQ + j * 8;
        uint32_t s = sb + (uint32_t)(r * 80 + j * 16);
        asm volatile("cp.async.ca.shared.global [%0], [%1], 16;" :: "r"(s), "l"(g));
    }
#pragma unroll
    for (int k = 0; k < 2; k++) {
        int t = tid + k * 256;
        int r = t >> 2, j = t & 3;
        const __half* g = bSrc + (size_t)r * kQ + j * 8;
        uint32_t s = sb + PL_BYTES + (uint32_t)(r * 80 + j * 16);
        asm volatile("cp.async.ca.shared.global [%0], [%1], 16;" :: "r"(s), "l"(g));
    }
}

// MMA over one resident stage: warp tile 32(M) x 64(N).
__device__ __forceinline__ void mma_stage(uint32_t sb, float (&acc)[2][8][4],
                                          int lane, int wm, int wn) {
    const int g = lane >> 3, l = lane & 7;
#pragma unroll
    for (int k16 = 0; k16 < 2; k16++) {
        uint32_t afrag[2][4];
        const int acol = k16 * 16 + (g >> 1) * 8;
#pragma unroll
        for (int mt = 0; mt < 2; mt++) {
            const int arow = wm + mt * 16 + (g & 1) * 8 + l;
            ldsm4(afrag[mt], sb + (uint32_t)(arow * SSTR + acol) * 2);
        }
        const int bcol = k16 * 16 + (g & 1) * 8;
#pragma unroll
        for (int np = 0; np < 4; np++) {
            const int brow = wn + np * 16 + (g >> 1) * 8 + l;
            uint32_t bfrag[4];
            ldsm4(bfrag, sb + PL_BYTES + (uint32_t)(brow * SSTR + bcol) * 2);
#pragma unroll
            for (int mt = 0; mt < 2; mt++) {
#pragma unroll
                for (int nt = 0; nt < 2; nt++) {
                    mma16816(acc[mt][np * 2 + nt], afrag[mt], &bfrag[nt * 2]);
                }
            }
        }
    }
}

// ---------------------------------------------------------------------------
// Converters
// ---------------------------------------------------------------------------
__global__ __launch_bounds__(256) void k_cvt_u(const float* __restrict__ src) {
    int i = blockIdx.x * blockDim.x + threadIdx.x;      // < kM*kQ/4
    float4 v = reinterpret_cast<const float4*>(src)[i];
    uint2 o; o.x = packh(v.x, v.y); o.y = packh(v.z, v.w);
    reinterpret_cast<uint2*>(g_u16)[i] = o;
}
__global__ __launch_bounds__(256) void k_cvt_w(const float* __restrict__ wb,
                                               const float* __restrict__ wc,
                                               const float* __restrict__ wd) {
    int i = blockIdx.x * blockDim.x + threadIdx.x;      // < 3*kQ*kQ/4
    const int per = kQ * kQ / 4;                         // 16384
    const float* s = (i < per) ? wb : (i < 2 * per ? wc : wd);
    __half* d = (i < per) ? g_WB16 : (i < 2 * per ? g_WC16 : g_WD16);
    int j = i % per;
    float4 v = reinterpret_cast<const float4*>(s)[j];
    uint2 o; o.x = packh(v.x, v.y); o.y = packh(v.z, v.w);
    reinterpret_cast<uint2*>(d)[j] = o;
}

// ---------------------------------------------------------------------------
// GEMM1: g_Bu = u16 @ WB16^T + bias (fp32 accum/out)
// ---------------------------------------------------------------------------
__global__ __launch_bounds__(256, 2) void k_mm_bu(const float* __restrict__ bias)
{
    extern __shared__ __half smem[];
    const int tid = threadIdx.x;
    const int bn = blockIdx.x, bm = blockIdx.y;
    const int tileRow = bm * TM;
    const int lane = tid & 31, wid = tid >> 5;
    const int wm = (wid & 3) * 32, wn = (wid >> 2) * 64;
    const uint32_t smb = smem_u32(smem);

    float acc[2][8][4];
#pragma unroll
    for (int a = 0; a < 2; a++)
#pragma unroll
        for (int b = 0; b < 8; b++)
#pragma unroll
            for (int c = 0; c < 4; c++) acc[a][b][c] = 0.0f;

    const __half* aBase = g_u16 + (size_t)tileRow * kQ;
    const __half* bBase = g_WB16 + (size_t)bn * TN * kQ;

    cpa_stage(smb, aBase, bBase, tid); CP_COMMIT();
    cpa_stage(smb + STAGE_BYTES, aBase + BK, bBase + BK, tid); CP_COMMIT();

    constexpr int C = 8;
    for (int c = 0; c < C; c++) {
        CP_WAIT1();
        __syncthreads();
        if (c + 2 < C)
            cpa_stage(smb + ((c + 2) % 3) * STAGE_BYTES,
                      aBase + (c + 2) * BK, bBase + (c + 2) * BK, tid);
        CP_COMMIT();
        mma_stage(smb + (c % 3) * STAGE_BYTES, acc, lane, wm, wn);
    }

    const int r0 = tileRow + wm + (lane >> 2);
    const int cb = bn * TN + wn;
#pragma unroll
    for (int mt = 0; mt < 2; mt++) {
        const int rr = r0 + mt * 16;
#pragma unroll
        for (int nt = 0; nt < 8; nt++) {
            const int cc = cb + nt * 8 + (lane & 3) * 2;
            const float b0 = bias[cc], b1 = bias[cc + 1];
            float2 lo, hi;
            lo.x = acc[mt][nt][0] + b0; lo.y = acc[mt][nt][1] + b1;
            hi.x = acc[mt][nt][2] + b0; hi.y = acc[mt][nt][3] + b1;
            *reinterpret_cast<float2*>(&g_Bu[(size_t)rr * kQ + cc]) = lo;
            *reinterpret_cast<float2*>(&g_Bu[(size_t)(rr + 8) * kQ + cc]) = hi;
        }
    }
}

// ---------------------------------------------------------------------------
// GEMM2: h = y16@WC16^T + u16@WD16^T + bC + bD; gelu+glu+residual epilogue
// ---------------------------------------------------------------------------
__global__ __launch_bounds__(256, 2) void k_mm_out(
    const float* __restrict__ U, const float* __restrict__ bC,
    const float* __restrict__ bD, float* __restrict__ Out)
{
    extern __shared__ __half smem[];
    const int tid = threadIdx.x;
    const int bn = blockIdx.x, bm = blockIdx.y;
    const int tileRow = bm * TM;
    const int lane = tid & 31, wid = tid >> 5;
    const int wm = (wid & 3) * 32, wn = (wid >> 2) * 64;
    const uint32_t smb = smem_u32(smem);

    float acc[2][8][4];
#pragma unroll
    for (int a = 0; a < 2; a++)
#pragma unroll
        for (int b = 0; b < 8; b++)
#pragma unroll
            for (int c = 0; c < 4; c++) acc[a][b][c] = 0.0f;

    constexpr int C = 16;
    auto aPtr = [&](int n) -> const __half* {
        return (n < 8 ? g_y16 : g_u16) + (size_t)tileRow * kQ + (n & 7) * BK;
    };
    auto bPtr = [&](int n) -> const __half* {
        return (n < 8 ? g_WC16 : g_WD16) + (size_t)bn * TN * kQ + (n & 7) * BK;
    };

    cpa_stage(smb, aPtr(0), bPtr(0), tid); CP_COMMIT();
    cpa_stage(smb + STAGE_BYTES, aPtr(1), bPtr(1), tid); CP_COMMIT();

    for (int c = 0; c < C; c++) {
        CP_WAIT1();
        __syncthreads();
        if (c + 2 < C)
            cpa_stage(smb + ((c + 2) % 3) * STAGE_BYTES, aPtr(c + 2), bPtr(c + 2), tid);
        CP_COMMIT();
        mma_stage(smb + (c % 3) * STAGE_BYTES, acc, lane, wm, wn);
    }

    const int r0 = tileRow + wm + (lane >> 2);
    const int cb = bn * TN + wn;
#pragma unroll
    for (int mt = 0; mt < 2; mt++) {
        const int rr = r0 + mt * 16;
#pragma unroll
        for (int nt = 0; nt < 8; nt++) {
            const int cc = cb + nt * 8 + (lane & 3) * 2;
            const float b0 = bC[cc] + bD[cc], b1 = bC[cc + 1] + bD[cc + 1];
#pragma unroll
            for (int half = 0; half < 2; half++) {
                const int row = rr + half * 8;
                float h0 = acc[mt][nt][half * 2 + 0] + b0;
                float h1 = acc[mt][nt][half * 2 + 1] + b1;
                float2 uv = *reinterpret_cast<const float2*>(&U[(size_t)row * kQ + cc]);
                float g0 = 0.5f * h0 * (1.0f + erff(h0 * 0.70710678118654752f));
                float g1 = 0.5f * h1 * (1.0f + erff(h1 * 0.70710678118654752f));
                float o0 = fmaf(g0, 1.0f / (1.0f + expf(-g0)), uv.x);
                float o1 = fmaf(g1, 1.0f / (1.0f + expf(-g1)), uv.y);
                float2 w; w.x = o0; w.y = o1;
                *reinterpret_cast<float2*>(&Out[(size_t)row * kQ + cc]) = w;
            }
        }
    }
}

// ---------------------------------------------------------------------------
// Scan (3-pass chunked, 64 chunks of 64)
// ---------------------------------------------------------------------------
__global__ __launch_bounds__(256) void k_scan_ends(const float* __restrict__ A)
{
    int idx = blockIdx.x * blockDim.x + threadIdx.x;
    int qi = idx & (kQ - 1);
    int c  = (idx >> 8) & (kNChunk - 1);
    int b  = idx >> 14;

    float av  = A[qi];
    float s   = 1.0f / (1.0f + kDT * kDT * av);
    float dts = kDT * s;
    float dsa = dts * av;

    const float* p = g_Bu + ((size_t)(b * kN + c * kCLen)) * kQ + qi;
    float x = 0.0f, z = 0.0f;
#pragma unroll 4
    for (int n = 0; n < kCLen; n++) {
        float bu = p[(size_t)n * kQ];
        float fx = dts * bu;
        float xn = fmaf(s, x, fmaf(-dsa, z, fx));
        float zn = fmaf(dts, x, fmaf(s, z, kDT * fx));
        x = xn; z = zn;
    }
    g_end[idx] = make_float2(x, z);
}

__global__ __launch_bounds__(256) void k_scan_combine(const float* __restrict__ A)
{
    int idx = blockIdx.x * blockDim.x + threadIdx.x;
    int qi = idx & (kQ - 1);
    int b  = idx >> 8;

    float av  = A[qi];
    float s   = 1.0f / (1.0f + kDT * kDT * av);
    float dts = kDT * s;
    float dsa = dts * av;

    float p00 = s, p01 = -dsa, p10 = dts, p11 = s;
#pragma unroll
    for (int i = 0; i < 6; i++) {          // M^(2^6) = M^kCLen
        float t   = p00 + p11;
        float bc  = p01 * p10;
        float n00 = fmaf(p00, p00, bc);
        float n01 = p01 * t;
        float n10 = p10 * t;
        float n11 = fmaf(p11, p11, bc);
        p00 = n00; p01 = n01; p10 = n10; p11 = n11;
    }

    float x = 0.0f, z = 0.0f;
#pragma unroll 8
    for (int c = 0; c < kNChunk; c++) {
        int gi = (b * kNChunk + c) * kQ + qi;
        g_init[gi] = make_float2(x, z);
        float2 e = g_end[gi];
        float xn = fmaf(p00, x, fmaf(p01, z, e.x));
        float zn = fmaf(p10, x, fmaf(p11, z, e.y));
        x = xn; z = zn;
    }
}

__global__ __launch_bounds__(256) void k_scan_emit(
    const float* __restrict__ A, float* __restrict__ Yout)
{
    int idx = blockIdx.x * blockDim.x + threadIdx.x;
    int qi = idx & (kQ - 1);
    int c  = (idx >> 8) & (kNChunk - 1);
    int b  = idx >> 14;

    float av  = A[qi];
    float s   = 1.0f / (1.0f + kDT * kDT * av);
    float dts = kDT * s;
    float dsa = dts * av;

    size_t off = ((size_t)(b * kN + c * kCLen)) * kQ + qi;
    const float* p = g_Bu + off;
    float* yp = Yout + off;
    __half* y16p = g_y16 + off;

    float2 st = g_init[idx];
    float x = st.x, z = st.y;
#pragma unroll 4
    for (int n = 0; n < kCLen; n++) {
        float bu = p[(size_t)n * kQ];
        float fx = dts * bu;
        float xn = fmaf(s, x, fmaf(-dsa, z, fx));
        float zn = fmaf(dts, x, fmaf(s, z, kDT * fx));
        x = xn; z = zn;
        yp[(size_t)n * kQ] = z;
        y16p[(size_t)n * kQ] = __float2half(z);
    }
}

// ---------------------------------------------------------------------------
// Launch
// ---------------------------------------------------------------------------
extern "C" void kernel_launch(void* const* d_in, const int* in_sizes, int n_in,
                              void* d_out, int out_size)
{
    const float* u  = (const float*)d_in[0];
    const float* a  = (const float*)d_in[1];
    const float* WB = (const float*)d_in[2];
    const float* bB = (const float*)d_in[3];
    const float* WC = (const float*)d_in[4];
    const float* bC = (const float*)d_in[5];
    const float* WD = (const float*)d_in[6];
    const float* bD = (const float*)d_in[7];

    float* out  = (float*)d_out;
    float* yout = out + (size_t)out_size / 2;

    static bool attr_done = false;
    if (!attr_done) {
        cudaFuncSetAttribute(k_mm_bu,  cudaFuncAttributeMaxDynamicSharedMemorySize, SMEM_BYTES);
        cudaFuncSetAttribute(k_mm_out, cudaFuncAttributeMaxDynamicSharedMemorySize, SMEM_BYTES);
        attr_done = true;
    }

    k_cvt_u<<<(kM * kQ / 4) / 256, 256>>>(u);
    k_cvt_w<<<(3 * kQ * kQ / 4) / 256, 256>>>(WB, WC, WD);

    dim3 grid(kQ / TN, kM / TM);                // (2, 512)
    k_mm_bu<<<grid, 256, SMEM_BYTES>>>(bB);

    int scanThreads = kB * kNChunk * kQ;        // 262144
    k_scan_ends<<<scanThreads / 256, 256>>>(a);
    k_scan_combine<<<(kB * kQ) / 256, 256>>>(a);
    k_scan_emit<<<scanThreads / 256, 256>>>(a, yout);

    k_mm_out<<<grid, 256, SMEM_BYTES>>>(u, bC, bD, out);
}